// round 1
// baseline (speedup 1.0000x reference)
#include <cuda_runtime.h>
#include <math.h>

#define NB 4
#define DD 16
#define HH 512
#define WW 512
#define PLANE (HH*WW)          // 262144
#define VOL (DD*PLANE)         // 4194304 per n
#define TOT (NB*VOL)           // 16777216
#define C1F 0.0001f
#define C2F 0.0009f

// Scratch: 5 2D-blurred fields (p, g, p^2, g^2, p*g), each [N,D,H,W]
__device__ float g_blur[5][TOT];
// Accumulators: [0..3] per-n sum of (p-g)^2 ; [4..7] per-n sum of ssim_map
__device__ double g_acc[8];

struct GaussW { float w[11]; };

__global__ void zero_acc_kernel() {
    int i = threadIdx.x;
    if (i < 8) g_acc[i] = 0.0;
}

// Fused W-blur + H-blur of all 5 fields for one (n,d) slice tile,
// with fused PSNR partial sums (interior of each tile covers the grid exactly once).
__global__ __launch_bounds__(256) void blur2d_kernel(
    const float* __restrict__ pred, const float* __restrict__ gt, GaussW gw)
{
    __shared__ float sp[42][45];
    __shared__ float sg[42][45];
    __shared__ float tmp[5][42][32];
    __shared__ float red[256];

    int z = blockIdx.z;            // z = n*16 + d
    int n = z >> 4;
    const float* pz = pred + (size_t)z * PLANE;
    const float* gz = gt   + (size_t)z * PLANE;
    int h0 = blockIdx.y * 32 - 5;
    int w0 = blockIdx.x * 32 - 5;
    int tid = threadIdx.x;

    // Load 42x42 tile (clamped = replicate padding)
    for (int i = tid; i < 42*42; i += 256) {
        int r = i / 42, c = i - r*42;
        int hh = min(max(h0 + r, 0), HH-1);
        int ww = min(max(w0 + c, 0), WW-1);
        sp[r][c] = pz[hh*WW + ww];
        sg[r][c] = gz[hh*WW + ww];
    }
    __syncthreads();

    // PSNR partial over interior 32x32 (each global element in exactly one interior)
    float psum = 0.f;
    for (int i = tid; i < 1024; i += 256) {
        int r = 5 + (i >> 5), c = 5 + (i & 31);
        float d = sp[r][c] - sg[r][c];
        psum = fmaf(d, d, psum);
    }

    // W-blur: 42 rows x 4 chunks of 8 outputs, 5 fields computed on the fly
    for (int it = tid; it < 168; it += 256) {
        int r = it >> 2, ch = (it & 3) * 8;
        float pv[18], gv[18];
        #pragma unroll
        for (int k = 0; k < 18; k++) { pv[k] = sp[r][ch+k]; gv[k] = sg[r][ch+k]; }
        #pragma unroll
        for (int o = 0; o < 8; o++) {
            float a0=0.f,a1=0.f,a2=0.f,a3=0.f,a4=0.f;
            #pragma unroll
            for (int k = 0; k < 11; k++) {
                float wgt = gw.w[k];
                float pp = pv[o+k], gg = gv[o+k];
                a0 = fmaf(wgt, pp, a0);
                a1 = fmaf(wgt, gg, a1);
                float wp = wgt * pp;
                a2 = fmaf(wp, pp, a2);
                a3 = fmaf(wgt*gg, gg, a3);
                a4 = fmaf(wp, gg, a4);
            }
            tmp[0][r][ch+o]=a0; tmp[1][r][ch+o]=a1; tmp[2][r][ch+o]=a2;
            tmp[3][r][ch+o]=a3; tmp[4][r][ch+o]=a4;
        }
    }
    __syncthreads();

    // H-blur + store: 5 fields x 4 h-chunks x 32 cols
    int hb = blockIdx.y * 32, wb = blockIdx.x * 32;
    for (int it = tid; it < 640; it += 256) {
        int c   = it & 31;
        int hch = (it >> 5) & 3;
        int f   = it >> 7;
        float v[18];
        #pragma unroll
        for (int k = 0; k < 18; k++) v[k] = tmp[f][hch*8+k][c];
        float* outf = &g_blur[f][(size_t)z * PLANE];
        #pragma unroll
        for (int o = 0; o < 8; o++) {
            float a = 0.f;
            #pragma unroll
            for (int k = 0; k < 11; k++) a = fmaf(gw.w[k], v[o+k], a);
            outf[(hb + hch*8 + o)*WW + wb + c] = a;
        }
    }

    // PSNR block reduce -> double atomic per n
    red[tid] = psum;
    __syncthreads();
    #pragma unroll
    for (int s = 128; s > 0; s >>= 1) {
        if (tid < s) red[tid] += red[tid+s];
        __syncthreads();
    }
    if (tid == 0) atomicAdd(&g_acc[n], (double)red[0]);
}

// D-blur (clamped, fully in registers since D=16) + SSIM pointwise + reduction
__global__ __launch_bounds__(256) void ssim_d_kernel(GaussW gw) {
    int tid = threadIdx.x;
    int idx = blockIdx.x * 256 + tid;     // position within (H,W) plane
    int n   = blockIdx.y;
    size_t base = (size_t)n * VOL + idx;

    float in0[16], in1[16], in2[16], in3[16], in4[16];
    #pragma unroll
    for (int d = 0; d < 16; d++) {
        size_t off = base + (size_t)d * PLANE;
        in0[d] = g_blur[0][off];
        in1[d] = g_blur[1][off];
        in2[d] = g_blur[2][off];
        in3[d] = g_blur[3][off];
        in4[d] = g_blur[4][off];
    }

    float ssum = 0.f;
    #pragma unroll
    for (int d = 0; d < 16; d++) {
        float b0=0.f,b1=0.f,b2=0.f,b3=0.f,b4=0.f;
        #pragma unroll
        for (int k = 0; k < 11; k++) {
            int dd = d - 5 + k;
            dd = dd < 0 ? 0 : (dd > 15 ? 15 : dd);   // compile-time after unroll
            float wgt = gw.w[k];
            b0 = fmaf(wgt, in0[dd], b0);
            b1 = fmaf(wgt, in1[dd], b1);
            b2 = fmaf(wgt, in2[dd], b2);
            b3 = fmaf(wgt, in3[dd], b3);
            b4 = fmaf(wgt, in4[dd], b4);
        }
        float mu1 = b0, mu2 = b1;
        float mu1s = mu1*mu1, mu2s = mu2*mu2, mu12 = mu1*mu2;
        float s1  = b2 - mu1s, s2 = b3 - mu2s, s12 = b4 - mu12;
        float v1  = 2.f*s12 + C2F;
        float v2  = s1 + s2 + C2F;
        float num = (2.f*mu12 + C1F) * v1;
        float den = (mu1s + mu2s + C1F) * v2;
        ssum += num / den;
    }

    __shared__ float red[256];
    red[tid] = ssum;
    __syncthreads();
    #pragma unroll
    for (int s = 128; s > 0; s >>= 1) {
        if (tid < s) red[tid] += red[tid+s];
        __syncthreads();
    }
    if (tid == 0) atomicAdd(&g_acc[4+n], (double)red[0]);
}

__global__ void final_kernel(float* out, int out_size) {
    if (threadIdx.x == 0 && blockIdx.x == 0) {
        double psnr = 0.0, ssim = 0.0;
        for (int n = 0; n < NB; n++) {
            double mse = g_acc[n] / (double)VOL;
            psnr += 10.0 * log10(1.0 / mse);
            ssim += g_acc[4+n] / (double)VOL;
        }
        if (out_size > 0) out[0] = (float)psnr;
        if (out_size > 1) out[1] = (float)ssim;
        if (out_size > 2) out[2] = (float)NB;
        for (int i = 3; i < out_size; i++) out[i] = 0.f;
    }
}

extern "C" void kernel_launch(void* const* d_in, const int* in_sizes, int n_in,
                              void* d_out, int out_size) {
    const float* pred = (const float*)d_in[0];
    const float* gt   = (const float*)d_in[1];

    // Gaussian weights, sigma=1.5, window 11 (computed in double on host)
    GaussW gw;
    double wd[11], s = 0.0;
    for (int i = 0; i < 11; i++) { double x = (double)(i - 5); wd[i] = exp(-x*x/4.5); s += wd[i]; }
    for (int i = 0; i < 11; i++) gw.w[i] = (float)(wd[i]/s);

    zero_acc_kernel<<<1, 32>>>();

    dim3 g1(WW/32, HH/32, NB*DD);
    blur2d_kernel<<<g1, 256>>>(pred, gt, gw);

    dim3 g2(PLANE/256, NB);
    ssim_d_kernel<<<g2, 256>>>(gw);

    final_kernel<<<1, 32>>>((float*)d_out, out_size);
}